// round 2
// baseline (speedup 1.0000x reference)
#include <cuda_runtime.h>
#include <cstdint>

#define BDIM 8192
#define KTOP 3
#define MARGIN 0.8f
#define NEG_FILL -50.0f

#define ROW_THREADS 256
#define VEC_PER_THREAD 8   // 8192 floats / 4 per float4 / 256 threads
#define NWARP (ROW_THREADS / 32)

__device__ float g_row_partial[BDIM];
__device__ unsigned int g_ctr = 0;

__device__ __forceinline__ void insert3(float& t0, float& t1, float& t2, float x) {
    if (x > t2) {
        if (x > t0)      { t2 = t1; t1 = t0; t0 = x; }
        else if (x > t1) { t2 = t1; t1 = x; }
        else             { t2 = x; }
    }
}

__global__ __launch_bounds__(ROW_THREADS, 4)
void fused_topk_loss_kernel(const float* __restrict__ inp, float* __restrict__ out) {
    const int row = blockIdx.x;
    const float4* __restrict__ rp =
        reinterpret_cast<const float4*>(inp + (size_t)row * BDIM);
    const int t = threadIdx.x;

    const int diag4 = row >> 2;      // which float4 of the row holds the diagonal
    const int diagl = row & 3;       // lane within that float4

    // ---- Phase 1: batch ALL loads up front (MLP_p1 = 8, 128 B/thread) ----
    float4 v[VEC_PER_THREAD];
    #pragma unroll
    for (int i = 0; i < VEC_PER_THREAD; i++)
        v[i] = __ldcs(&rp[t + i * ROW_THREADS]);   // streaming: no reuse

    // ---- mask the diagonal (positive) out of the candidate set ----
    #pragma unroll
    for (int i = 0; i < VEC_PER_THREAD; i++) {
        if (t + i * ROW_THREADS == diag4) {
            if      (diagl == 0) v[i].x = -1e30f;
            else if (diagl == 1) v[i].y = -1e30f;
            else if (diagl == 2) v[i].z = -1e30f;
            else                 v[i].w = -1e30f;
        }
    }

    // ---- Phase 2: top-3 scan; branch once per float4 via group max ----
    float t0 = -1e30f, t1 = -1e30f, t2 = -1e30f;
    #pragma unroll
    for (int i = 0; i < VEC_PER_THREAD; i++) {
        const float m01 = fmaxf(v[i].x, v[i].y);
        const float m23 = fmaxf(v[i].z, v[i].w);
        const float gm  = fmaxf(m01, m23);
        if (gm > t2) {                 // rare after warm-up
            insert3(t0, t1, t2, v[i].x);
            insert3(t0, t1, t2, v[i].y);
            insert3(t0, t1, t2, v[i].z);
            insert3(t0, t1, t2, v[i].w);
        }
    }

    // ---- warp merge ----
    #pragma unroll
    for (int off = 16; off > 0; off >>= 1) {
        float a0 = __shfl_down_sync(0xFFFFFFFFu, t0, off);
        float a1 = __shfl_down_sync(0xFFFFFFFFu, t1, off);
        float a2 = __shfl_down_sync(0xFFFFFFFFu, t2, off);
        insert3(t0, t1, t2, a0);
        insert3(t0, t1, t2, a1);
        insert3(t0, t1, t2, a2);
    }

    __shared__ float sm[NWARP][3];
    __shared__ int s_last;
    const int wid = t >> 5;
    const int lid = t & 31;
    if (lid == 0) { sm[wid][0] = t0; sm[wid][1] = t1; sm[wid][2] = t2; }
    __syncthreads();

    if (t == 0) {
        #pragma unroll
        for (int w = 1; w < NWARP; w++) {
            insert3(t0, t1, t2, sm[w][0]);
            insert3(t0, t1, t2, sm[w][1]);
            insert3(t0, t1, t2, sm[w][2]);
        }

        // ---- epilogue: hinge + softmax re-weighting (K=3, tau=0.1) ----
        const float sp = inp[(size_t)row * BDIM + row];

        float l0 = fmaxf(t0 - sp + MARGIN, 0.0f);
        float l1 = fmaxf(t1 - sp + MARGIN, 0.0f);
        float l2 = fmaxf(t2 - sp + MARGIN, 0.0f);

        float m0 = (l0 == 0.0f) ? NEG_FILL : t0;
        float m1 = (l1 == 0.0f) ? NEG_FILL : t1;
        float m2 = (l2 == 0.0f) ? NEG_FILL : t2;

        float mm = fmaxf(m0, fmaxf(m1, m2));
        float e0 = __expf((m0 - mm) * 10.0f);   // /tau = *10
        float e1 = __expf((m1 - mm) * 10.0f);
        float e2 = __expf((m2 - mm) * 10.0f);
        float s  = e0 + e1 + e2;

        g_row_partial[row] = (l0 * e0 + l1 * e1 + l2 * e2) / s;

        __threadfence();
        unsigned c = atomicAdd(&g_ctr, 1u);
        s_last = (c == (unsigned)(gridDim.x - 1)) ? 1 : 0;
    }
    __syncthreads();

    // ---- last CTA: final mean reduction (replaces the tail kernel) ----
    if (s_last) {
        float acc = 0.0f;
        #pragma unroll
        for (int i = 0; i < BDIM / ROW_THREADS; i++)
            acc += __ldcg(&g_row_partial[t + i * ROW_THREADS]);

        #pragma unroll
        for (int off = 16; off > 0; off >>= 1)
            acc += __shfl_down_sync(0xFFFFFFFFu, acc, off);

        __shared__ float rsm[NWARP];
        if (lid == 0) rsm[wid] = acc;
        __syncthreads();

        if (t == 0) {
            float s = 0.0f;
            #pragma unroll
            for (int w = 0; w < NWARP; w++) s += rsm[w];
            out[0] = s / (float)(BDIM * KTOP);
            g_ctr = 0;   // reset for next graph replay (deterministic)
        }
    }
}

extern "C" void kernel_launch(void* const* d_in, const int* in_sizes, int n_in,
                              void* d_out, int out_size) {
    const float* inp = (const float*)d_in[0];
    // d_in[1] is target == eye(B); masking reduces to diagonal exclusion, so unused.
    float* out = (float*)d_out;

    fused_topk_loss_kernel<<<BDIM, ROW_THREADS>>>(inp, out);
}

// round 3
// speedup vs baseline: 1.4860x; 1.4860x over previous
#include <cuda_runtime.h>
#include <cstdint>

#define BDIM 8192
#define KTOP 3
#define MARGIN 0.8f
#define NEG_FILL -50.0f

#define ROW_THREADS 256
#define VEC_PER_THREAD 8   // 8192 floats / 4 per float4 / 256 threads
#define NWARP (ROW_THREADS / 32)

__device__ float g_row_partial[BDIM];
__device__ unsigned int g_ctr = 0;

// Merge sorted-descending triple (b0,b1,b2) into sorted-descending triple
// (t0,t1,t2). 7 FMNMX, branchless.
// Identities: 1st = max(a0,b0); 2nd = max(min(a0,b0), max(a1,b1));
// 3rd = max(min(min(a0,b0), max(a1,b1)), a2, b2).
__device__ __forceinline__ void merge3(float& t0, float& t1, float& t2,
                                       float b0, float b1, float b2) {
    const float u = fminf(t0, b0);
    const float q = fmaxf(t1, b1);
    const float z = fminf(u, q);
    t0 = fmaxf(t0, b0);
    t1 = fmaxf(u, q);
    t2 = fmaxf(fmaxf(z, t2), b2);
}

// Sorted-descending top-3 of a float4. 9 FMNMX, branchless.
// (min of the two pair-mins can never be in the top-3 of 4.)
__device__ __forceinline__ void sort4_top3(float4 v, float& s0, float& s1, float& s2) {
    const float m01 = fmaxf(v.x, v.y), n01 = fminf(v.x, v.y);
    const float m23 = fmaxf(v.z, v.w), n23 = fminf(v.z, v.w);
    const float a = fmaxf(m01, m23);
    const float b = fminf(m01, m23);
    const float c = fmaxf(n01, n23);
    s0 = a;
    s1 = fmaxf(b, c);
    s2 = fminf(b, c);
}

__global__ __launch_bounds__(ROW_THREADS, 5)
void fused_topk_loss_kernel(const float* __restrict__ inp, float* __restrict__ out) {
    const int row = blockIdx.x;
    const float4* __restrict__ rp =
        reinterpret_cast<const float4*>(inp + (size_t)row * BDIM);
    const int t = threadIdx.x;

    // ---- batch ALL loads up front (8x LDG.128 in flight) ----
    float4 v[VEC_PER_THREAD];
    #pragma unroll
    for (int i = 0; i < VEC_PER_THREAD; i++)
        v[i] = rp[t + i * ROW_THREADS];

    // ---- mask the diagonal (positive): exactly ONE thread per CTA ----
    const int diag4 = row >> 2;                 // float4 index of diagonal in row
    const int diagl = row & 3;                  // component within that float4
    if (t == (diag4 & (ROW_THREADS - 1))) {     // cold branch, 1 warp diverges
        const int slot = diag4 >> 8;            // which of the 8 batched float4s
        #pragma unroll
        for (int i = 0; i < VEC_PER_THREAD; i++) {
            if (i == slot) {
                if      (diagl == 0) v[i].x = -1e30f;
                else if (diagl == 1) v[i].y = -1e30f;
                else if (diagl == 2) v[i].z = -1e30f;
                else                 v[i].w = -1e30f;
            }
        }
    }

    // ---- branchless top-3 scan: 16 FMNMX per float4 ----
    float t0, t1, t2;
    sort4_top3(v[0], t0, t1, t2);
    #pragma unroll
    for (int i = 1; i < VEC_PER_THREAD; i++) {
        float s0, s1, s2;
        sort4_top3(v[i], s0, s1, s2);
        merge3(t0, t1, t2, s0, s1, s2);
    }

    // ---- warp merge (triples stay sorted; 3 SHFL + 7 FMNMX per round) ----
    #pragma unroll
    for (int off = 16; off > 0; off >>= 1) {
        const float a0 = __shfl_down_sync(0xFFFFFFFFu, t0, off);
        const float a1 = __shfl_down_sync(0xFFFFFFFFu, t1, off);
        const float a2 = __shfl_down_sync(0xFFFFFFFFu, t2, off);
        merge3(t0, t1, t2, a0, a1, a2);
    }

    __shared__ float sm[NWARP][3];
    __shared__ int s_last;
    const int wid = t >> 5;
    const int lid = t & 31;
    if (lid == 0) { sm[wid][0] = t0; sm[wid][1] = t1; sm[wid][2] = t2; }
    __syncthreads();

    if (t == 0) {
        #pragma unroll
        for (int w = 1; w < NWARP; w++)
            merge3(t0, t1, t2, sm[w][0], sm[w][1], sm[w][2]);

        // ---- epilogue: hinge + softmax re-weighting (K=3, tau=0.1) ----
        const float sp = inp[(size_t)row * BDIM + row];

        const float l0 = fmaxf(t0 - sp + MARGIN, 0.0f);
        const float l1 = fmaxf(t1 - sp + MARGIN, 0.0f);
        const float l2 = fmaxf(t2 - sp + MARGIN, 0.0f);

        const float m0 = (l0 == 0.0f) ? NEG_FILL : t0;
        const float m1 = (l1 == 0.0f) ? NEG_FILL : t1;
        const float m2 = (l2 == 0.0f) ? NEG_FILL : t2;

        const float mm = fmaxf(m0, fmaxf(m1, m2));
        const float e0 = __expf((m0 - mm) * 10.0f);   // /tau = *10
        const float e1 = __expf((m1 - mm) * 10.0f);
        const float e2 = __expf((m2 - mm) * 10.0f);
        const float s  = e0 + e1 + e2;

        g_row_partial[row] = (l0 * e0 + l1 * e1 + l2 * e2) / s;

        __threadfence();
        const unsigned c = atomicAdd(&g_ctr, 1u);
        s_last = (c == (unsigned)(gridDim.x - 1)) ? 1 : 0;
    }
    __syncthreads();

    // ---- last CTA: final mean reduction (no tail kernel) ----
    if (s_last) {
        float acc = 0.0f;
        #pragma unroll
        for (int i = 0; i < BDIM / ROW_THREADS; i++)
            acc += __ldcg(&g_row_partial[t + i * ROW_THREADS]);

        #pragma unroll
        for (int off = 16; off > 0; off >>= 1)
            acc += __shfl_down_sync(0xFFFFFFFFu, acc, off);

        __shared__ float rsm[NWARP];
        if (lid == 0) rsm[wid] = acc;
        __syncthreads();

        if (t == 0) {
            float s = 0.0f;
            #pragma unroll
            for (int w = 0; w < NWARP; w++) s += rsm[w];
            out[0] = s / (float)(BDIM * KTOP);
            g_ctr = 0;   // reset for next graph replay (deterministic)
        }
    }
}

extern "C" void kernel_launch(void* const* d_in, const int* in_sizes, int n_in,
                              void* d_out, int out_size) {
    const float* inp = (const float*)d_in[0];
    // d_in[1] is target == eye(B); masking reduces to diagonal exclusion, so unused.
    float* out = (float*)d_out;

    fused_topk_loss_kernel<<<BDIM, ROW_THREADS>>>(inp, out);
}

// round 4
// speedup vs baseline: 1.4933x; 1.0049x over previous
#include <cuda_runtime.h>
#include <cstdint>

#define BDIM 8192
#define KTOP 3
#define MARGIN 0.8f
#define NEG_FILL -50.0f

#define ROW_THREADS 512
#define VEC_PER_THREAD 4   // 8192 floats / 4 per float4 / 512 threads
#define NWARP (ROW_THREADS / 32)

__device__ float g_row_partial[BDIM];
__device__ unsigned int g_ctr = 0;

// Merge sorted-descending triple (b0,b1,b2) into (t0,t1,t2). 7 FMNMX, branchless.
__device__ __forceinline__ void merge3(float& t0, float& t1, float& t2,
                                       float b0, float b1, float b2) {
    const float u = fminf(t0, b0);
    const float q = fmaxf(t1, b1);
    const float z = fminf(u, q);
    t0 = fmaxf(t0, b0);
    t1 = fmaxf(u, q);
    t2 = fmaxf(fmaxf(z, t2), b2);
}

// Sorted-descending top-3 of a float4. 9 FMNMX, branchless.
__device__ __forceinline__ void sort4_top3(float4 v, float& s0, float& s1, float& s2) {
    const float m01 = fmaxf(v.x, v.y), n01 = fminf(v.x, v.y);
    const float m23 = fmaxf(v.z, v.w), n23 = fminf(v.z, v.w);
    const float b = fminf(m01, m23);
    const float c = fmaxf(n01, n23);
    s0 = fmaxf(m01, m23);
    s1 = fmaxf(b, c);
    s2 = fminf(b, c);
}

__global__ __launch_bounds__(ROW_THREADS, 4)
void fused_topk_loss_kernel(const float* __restrict__ inp, float* __restrict__ out) {
    const int row = blockIdx.x;
    const float4* __restrict__ rp =
        reinterpret_cast<const float4*>(inp + (size_t)row * BDIM);
    const int t = threadIdx.x;

    // ---- batch ALL loads up front (4x LDG.128 in flight per thread) ----
    float4 v[VEC_PER_THREAD];
    #pragma unroll
    for (int i = 0; i < VEC_PER_THREAD; i++)
        v[i] = rp[t + i * ROW_THREADS];

    // ---- mask the diagonal (positive): exactly ONE thread per CTA ----
    const int diag4 = row >> 2;                 // float4 index of diagonal in row
    const int diagl = row & 3;                  // component within that float4
    if (t == (diag4 & (ROW_THREADS - 1))) {     // cold branch, 1 warp diverges
        const int slot = diag4 >> 9;            // which of the 4 batched float4s
        #pragma unroll
        for (int i = 0; i < VEC_PER_THREAD; i++) {
            if (i == slot) {
                if      (diagl == 0) v[i].x = -1e30f;
                else if (diagl == 1) v[i].y = -1e30f;
                else if (diagl == 2) v[i].z = -1e30f;
                else                 v[i].w = -1e30f;
            }
        }
    }

    // ---- branchless top-3 scan: 16 FMNMX per float4 ----
    float t0, t1, t2;
    sort4_top3(v[0], t0, t1, t2);
    #pragma unroll
    for (int i = 1; i < VEC_PER_THREAD; i++) {
        float s0, s1, s2;
        sort4_top3(v[i], s0, s1, s2);
        merge3(t0, t1, t2, s0, s1, s2);
    }

    // ---- warp merge (triples stay sorted; 3 SHFL + 7 FMNMX per round) ----
    #pragma unroll
    for (int off = 16; off > 0; off >>= 1) {
        const float a0 = __shfl_down_sync(0xFFFFFFFFu, t0, off);
        const float a1 = __shfl_down_sync(0xFFFFFFFFu, t1, off);
        const float a2 = __shfl_down_sync(0xFFFFFFFFu, t2, off);
        merge3(t0, t1, t2, a0, a1, a2);
    }

    __shared__ float sm[NWARP][3];
    __shared__ int s_last;
    const int wid = t >> 5;
    const int lid = t & 31;
    if (lid == 0) { sm[wid][0] = t0; sm[wid][1] = t1; sm[wid][2] = t2; }
    __syncthreads();

    if (t == 0) {
        #pragma unroll
        for (int w = 1; w < NWARP; w++)
            merge3(t0, t1, t2, sm[w][0], sm[w][1], sm[w][2]);

        // ---- epilogue: hinge + softmax re-weighting (K=3, tau=0.1) ----
        const float sp = inp[(size_t)row * BDIM + row];

        const float l0 = fmaxf(t0 - sp + MARGIN, 0.0f);
        const float l1 = fmaxf(t1 - sp + MARGIN, 0.0f);
        const float l2 = fmaxf(t2 - sp + MARGIN, 0.0f);

        const float m0 = (l0 == 0.0f) ? NEG_FILL : t0;
        const float m1 = (l1 == 0.0f) ? NEG_FILL : t1;
        const float m2 = (l2 == 0.0f) ? NEG_FILL : t2;

        const float mm = fmaxf(m0, fmaxf(m1, m2));
        const float e0 = __expf((m0 - mm) * 10.0f);   // /tau = *10
        const float e1 = __expf((m1 - mm) * 10.0f);
        const float e2 = __expf((m2 - mm) * 10.0f);
        const float s  = e0 + e1 + e2;

        g_row_partial[row] = (l0 * e0 + l1 * e1 + l2 * e2) / s;

        __threadfence();
        const unsigned c = atomicAdd(&g_ctr, 1u);
        s_last = (c == (unsigned)(gridDim.x - 1)) ? 1 : 0;
    }
    __syncthreads();

    // ---- last CTA: final mean reduction (no tail kernel) ----
    if (s_last) {
        float acc = 0.0f;
        #pragma unroll
        for (int i = 0; i < BDIM / ROW_THREADS; i++)
            acc += __ldcg(&g_row_partial[t + i * ROW_THREADS]);

        #pragma unroll
        for (int off = 16; off > 0; off >>= 1)
            acc += __shfl_down_sync(0xFFFFFFFFu, acc, off);

        __shared__ float rsm[NWARP];
        if (lid == 0) rsm[wid] = acc;
        __syncthreads();

        if (t == 0) {
            float s = 0.0f;
            #pragma unroll
            for (int w = 0; w < NWARP; w++) s += rsm[w];
            out[0] = s / (float)(BDIM * KTOP);
            g_ctr = 0;   // reset for next graph replay (deterministic)
        }
    }
}

extern "C" void kernel_launch(void* const* d_in, const int* in_sizes, int n_in,
                              void* d_out, int out_size) {
    const float* inp = (const float*)d_in[0];
    // d_in[1] is target == eye(B); masking reduces to diagonal exclusion, so unused.
    float* out = (float*)d_out;

    fused_topk_loss_kernel<<<BDIM, ROW_THREADS>>>(inp, out);
}